// round 4
// baseline (speedup 1.0000x reference)
#include <cuda_runtime.h>
#include <cuda_bf16.h>

// Problem constants
#define BATCH 128
#define BINS 128
#define HW 262144               // 512*512 elements per batch (C=1)
#define TOTAL (BATCH * HW)      // 33554432
#define HIST_BPB 4              // histogram blocks per batch
#define HIST_THREADS 128
#define CHUNK (HW / HIST_BPB)   // 65536 elements per hist block

// Scratch (device globals: no allocations allowed)
__device__ float g_part[BATCH * HIST_BPB * BINS];   // per-(batch,part) partial hist
__device__ float g_w[BATCH];

// ---------------------------------------------------------------------------
// Kernel 1: per-batch histogram.
// Per-thread private uint16 counters in shared memory, CONFLICT-FREE layout:
//   counter(bin, t) lives at uint16 index  bin*128 + (t&63)*2 + (t>>6)
// -> threads t and t+64 share one 32-bit word (different halves: byte-enabled,
//    no conflict), and within a warp the bank is ((t&63)%32): distinct per
//    lane, INDEPENDENT of bin. RMW = 1-cyc LDS + 1-cyc STS, zero replays.
// 32 KB smem/block -> 7 blocks/SM -> 512-block grid fits in one wave.
// Epilogue: plain stores of per-block partials (no atomics, no zero kernel).
// ---------------------------------------------------------------------------
__global__ void __launch_bounds__(HIST_THREADS) hist_kernel(const float* __restrict__ x) {
    __shared__ unsigned short sh[BINS * HIST_THREADS];   // 32 KB
    unsigned int* sh32 = reinterpret_cast<unsigned int*>(sh);

    const int t = threadIdx.x;

    // zero (8192 words / 128 threads = 64 each, bank = t%32: conflict-free)
    #pragma unroll
    for (int i = 0; i < 64; i++)
        sh32[i * HIST_THREADS + t] = 0u;
    __syncthreads();

    const int batch = blockIdx.x >> 2;        // / HIST_BPB
    const int part  = blockIdx.x & (HIST_BPB - 1);
    const int lane_off = (t & 63) * 2 + (t >> 6);   // uint16 offset within a bin row

    const float4* xp = reinterpret_cast<const float4*>(x)
                     + (size_t)batch * (HW / 4) + (size_t)part * (CHUNK / 4);

    // CHUNK/4 = 16384 float4 per block, 128 threads -> 128 iterations
    #pragma unroll 8
    for (int i = t; i < CHUNK / 4; i += HIST_THREADS) {
        float4 v = xp[i];
        {
            float f = v.x;
            int bin = __float2int_rd(f * 128.0f);
            bin = min(max(bin, 0), BINS - 1);
            if (f >= 0.0f && f <= 1.0f) sh[bin * HIST_THREADS + lane_off]++;
        }
        {
            float f = v.y;
            int bin = __float2int_rd(f * 128.0f);
            bin = min(max(bin, 0), BINS - 1);
            if (f >= 0.0f && f <= 1.0f) sh[bin * HIST_THREADS + lane_off]++;
        }
        {
            float f = v.z;
            int bin = __float2int_rd(f * 128.0f);
            bin = min(max(bin, 0), BINS - 1);
            if (f >= 0.0f && f <= 1.0f) sh[bin * HIST_THREADS + lane_off]++;
        }
        {
            float f = v.w;
            int bin = __float2int_rd(f * 128.0f);
            bin = min(max(bin, 0), BINS - 1);
            if (f >= 0.0f && f <= 1.0f) sh[bin * HIST_THREADS + lane_off]++;
        }
    }
    __syncthreads();

    // Reduce: thread t sums all 128 counters of bin t (row t = 64 uint32 words,
    // each holding two uint16 counters). Rotated read j=(t+i)&63 -> bank
    // ((t+i)&63)%32: distinct per lane, conflict-free.
    unsigned int s = 0;
    #pragma unroll
    for (int i = 0; i < 64; i++) {
        int j = (t + i) & 63;
        unsigned int v = sh32[t * 64 + j];
        s += (v & 0xFFFFu) + (v >> 16);
    }
    g_part[(batch * HIST_BPB + part) * BINS + t] = (float)s;
}

// ---------------------------------------------------------------------------
// Kernel 2: tiny MLP. One block, 128 threads; thread b handles batch b.
//   hist[b][k] = sum_p g_part[b][p][k]
//   h = relu(hist[b] @ W1 + b1)   (128x16)
//   w = h @ W2 + b2               (16x1)
// ---------------------------------------------------------------------------
__global__ void __launch_bounds__(BATCH) mlp_kernel(const float* __restrict__ W1,
                                                    const float* __restrict__ b1,
                                                    const float* __restrict__ W2,
                                                    const float* __restrict__ b2) {
    const int b = threadIdx.x;
    float h[16];
    #pragma unroll
    for (int j = 0; j < 16; j++) h[j] = b1[j];

    const float* pp = g_part + b * HIST_BPB * BINS;

    #pragma unroll 4
    for (int k = 0; k < BINS; k++) {
        float c = pp[k] + pp[BINS + k] + pp[2 * BINS + k] + pp[3 * BINS + k];
        #pragma unroll
        for (int j = 0; j < 16; j++)
            h[j] = fmaf(c, W1[k * 16 + j], h[j]);
    }

    float w = b2[0];
    #pragma unroll
    for (int j = 0; j < 16; j++)
        w = fmaf(fmaxf(h[j], 0.0f), W2[j], w);

    g_w[b] = w;
}

// ---------------------------------------------------------------------------
// Kernel 3: out = x * w[batch]. float4 vectorized; 65536 float4 per batch so
// batch = vec_idx >> 16 (warp-uniform).
// ---------------------------------------------------------------------------
__global__ void __launch_bounds__(256) scale_kernel(const float* __restrict__ x,
                                                    float* __restrict__ out) {
    size_t vi = (size_t)blockIdx.x * blockDim.x + threadIdx.x;
    float w = g_w[vi >> 16];
    float4 v = reinterpret_cast<const float4*>(x)[vi];
    v.x *= w; v.y *= w; v.z *= w; v.w *= w;
    reinterpret_cast<float4*>(out)[vi] = v;
}

// ---------------------------------------------------------------------------
// Launch
// ---------------------------------------------------------------------------
extern "C" void kernel_launch(void* const* d_in, const int* in_sizes, int n_in,
                              void* d_out, int out_size) {
    const float* x  = (const float*)d_in[0];
    const float* W1 = (const float*)d_in[1];
    const float* b1 = (const float*)d_in[2];
    const float* W2 = (const float*)d_in[3];
    const float* b2 = (const float*)d_in[4];
    float* out = (float*)d_out;

    hist_kernel<<<BATCH * HIST_BPB, HIST_THREADS>>>(x);
    mlp_kernel<<<1, BATCH>>>(W1, b1, W2, b2);
    scale_kernel<<<(TOTAL / 4) / 256, 256>>>(x, out);
}